// round 13
// baseline (speedup 1.0000x reference)
#include <cuda_runtime.h>
#include <math.h>

#define NN   50000
#define FIN  17
#define HID  64
#define EE   400000
#define ENT  450000   // EE + NN self loops
#define GS   128      // BN partial-sum slots
#define SCAN_BLK 512
#define SCAN_NB  98   // ceil(NN/512)

// ---------------- scratch (static __device__, no allocation) ----------------
__device__ __align__(16) float d_h0[NN * HID];   // node features (ping)
__device__ __align__(16) float d_h1[NN * HID];   // node features (pong)
__device__ __align__(16) float d_g[NN * HID];    // pre-BN buffer
__device__ __align__(16) float d_xlxr[NN * 256]; // [xl(128) | xr(128)] per node
__device__ double d_psum[GS * HID];              // BN partial sums (atomic slots)
__device__ double d_psq[GS * HID];               // BN partial sums of squares
__device__ __align__(16) float d_scale[HID];     // folded BN scale
__device__ __align__(16) float d_shift[HID];     // folded BN shift
__device__ int    d_deg[NN];
__device__ int    d_rowptr[NN + 1];
__device__ int    d_cursor[NN];
__device__ int    d_csrc[ENT];
__device__ int    d_bsum[SCAN_NB];

__device__ __forceinline__ float eluf(float v)  { return v > 0.f ? v : expm1f(v); }
__device__ __forceinline__ float lrelu(float v) { return v > 0.f ? v : 0.2f * v; }

// ================= CSR build =================
__global__ void k_zero_deg() {
    int i = blockIdx.x * blockDim.x + threadIdx.x;
    if (i < NN) d_deg[i] = 0;
}
__global__ void k_count(const int* __restrict__ ei) {
    int i = blockIdx.x * blockDim.x + threadIdx.x;
    if (i >= ENT) return;
    int dst = (i < EE) ? ei[EE + i] : (i - EE);
    atomicAdd(&d_deg[dst], 1);
}
__global__ void k_scan1() {
    __shared__ int sm[SCAN_BLK];
    int i = blockIdx.x * SCAN_BLK + threadIdx.x;
    sm[threadIdx.x] = (i < NN) ? d_deg[i] : 0;
    __syncthreads();
    for (int o = SCAN_BLK / 2; o; o >>= 1) {
        if (threadIdx.x < o) sm[threadIdx.x] += sm[threadIdx.x + o];
        __syncthreads();
    }
    if (threadIdx.x == 0) d_bsum[blockIdx.x] = sm[0];
}
__global__ void k_scan2() {
    int acc = 0;
    for (int b = 0; b < SCAN_NB; b++) { int t = d_bsum[b]; d_bsum[b] = acc; acc += t; }
}
__global__ void k_scan3() {
    __shared__ int sm[SCAN_BLK];
    int i = blockIdx.x * SCAN_BLK + threadIdx.x;
    int v = (i < NN) ? d_deg[i] : 0;
    sm[threadIdx.x] = v;
    __syncthreads();
    for (int o = 1; o < SCAN_BLK; o <<= 1) {
        int t = (threadIdx.x >= o) ? sm[threadIdx.x - o] : 0;
        __syncthreads();
        sm[threadIdx.x] += t;
        __syncthreads();
    }
    int excl = sm[threadIdx.x] - v + d_bsum[blockIdx.x];
    if (i < NN) {
        d_rowptr[i] = excl;
        d_cursor[i] = excl;
        if (i == NN - 1) d_rowptr[NN] = excl + v;
    }
}
__global__ void k_scatter(const int* __restrict__ ei) {
    int i = blockIdx.x * blockDim.x + threadIdx.x;
    if (i >= ENT) return;
    int src, dst;
    if (i < EE) { src = ei[i]; dst = ei[EE + i]; } else { src = i - EE; dst = src; }
    int pos = atomicAdd(&d_cursor[dst], 1);
    d_csrc[pos] = src;
}

// ---------------- input projection + BN stats. blockDim (64,4), grid GS ----
__global__ void k_in_proj(const float* __restrict__ x,
                          const float* __restrict__ W,
                          const float* __restrict__ b) {
    int c = threadIdx.x, ty = threadIdx.y;
    float wcol[FIN];
#pragma unroll
    for (int k = 0; k < FIN; k++) wcol[k] = W[k * HID + c];
    float bias = b[c];
    double s = 0.0, ss = 0.0;
    for (int n = blockIdx.x * 4 + ty; n < NN; n += GS * 4) {
        const float* xr = x + n * FIN;
        float acc = bias;
#pragma unroll
        for (int k = 0; k < FIN; k++) acc += xr[k] * wcol[k];
        d_g[n * HID + c] = acc;
        s += acc; ss += (double)acc * acc;
    }
    __shared__ double sm[4][HID], sm2[4][HID];
    sm[ty][c] = s; sm2[ty][c] = ss;
    __syncthreads();
    if (ty == 0) {
        d_psum[blockIdx.x * HID + c] = sm[0][c] + sm[1][c] + sm[2][c] + sm[3][c];
        d_psq [blockIdx.x * HID + c] = sm2[0][c] + sm2[1][c] + sm2[2][c] + sm2[3][c];
    }
}

// ---- fold BN into scale/shift, then zero the accumulator slots. 1x64 ------
__global__ void k_bn_prep(const float* __restrict__ gamma,
                          const float* __restrict__ beta) {
    int c = threadIdx.x;
    double s = 0.0, ss = 0.0;
    for (int i = 0; i < GS; i++) { s += d_psum[i * HID + c]; ss += d_psq[i * HID + c]; }
    double m   = s / (double)NN;
    double var = ss / (double)NN - m * m;
    double rs  = 1.0 / sqrt(var + 1e-5);
    double g   = (double)gamma[c] * rs;
    d_scale[c] = (float)g;
    d_shift[c] = (float)((double)beta[c] - m * g);
    for (int i = 0; i < GS; i++) { d_psum[i * HID + c] = 0.0; d_psq[i * HID + c] = 0.0; }
}

// ---------------- GEMM with fused BN-apply + ELU + residual ----------------
// A = h_layer = elu(g*scale+shift) (+ h_old). blockIdx.y==0 also writes h out.
// 256 threads, tile 128(rows) x 128(cols), K in 2 panels of 32. grid (391, 2).
// Microtile 8x8 -> 4 LDS.128 per 64 FFMA (FFMA-issue bound).
__global__ void __launch_bounds__(256, 2)
k_gemm(const float* __restrict__ Wlp, const float* __restrict__ Wrp, int layer) {
    __shared__ float As[32 * 128];   // K-panel major: As[k][r]
    __shared__ float Bs[32 * 128];   // Bs[k][j]
    int tid = threadIdx.x;
    int bn = blockIdx.y;             // 0 -> Wl, 1 -> Wr
    int row0 = blockIdx.x * 128;

    const float4* G4  = (const float4*)d_g;
    const float4* HO4 = (layer & 1) ? (const float4*)d_h0 : (const float4*)d_h1;
    float4*       HW4 = (layer & 1) ? (float4*)d_h1 : (float4*)d_h0;
    int  res = (layer > 0);
    bool wr  = (bn == 0);
    const float* Ws = bn ? Wrp : Wlp;

    int tx = tid & 15, ty = tid >> 4;      // 16 col-groups x 16 row-groups
    float acc[8][8] = {};

    for (int kp = 0; kp < 2; kp++) {
        // A panel: 128 rows x 32 k; BN+ELU(+residual) applied on the fly
        for (int f = tid; f < 1024; f += 256) {
            int r = f & 127, k4l = f >> 7;          // k4l 0..7
            int k4 = kp * 8 + k4l;
            float4 v = make_float4(0.f, 0.f, 0.f, 0.f);
            int row = row0 + r;
            if (row < NN) {
                float4 gg = G4[row * 16 + k4];
                float4 sc = ((const float4*)d_scale)[k4];
                float4 sh = ((const float4*)d_shift)[k4];
                v.x = eluf(fmaf(gg.x, sc.x, sh.x));
                v.y = eluf(fmaf(gg.y, sc.y, sh.y));
                v.z = eluf(fmaf(gg.z, sc.z, sh.z));
                v.w = eluf(fmaf(gg.w, sc.w, sh.w));
                if (res) {
                    float4 ho = HO4[row * 16 + k4];
                    v.x += ho.x; v.y += ho.y; v.z += ho.z; v.w += ho.w;
                }
                if (wr) HW4[row * 16 + k4] = v;
            }
            As[(k4l * 4 + 0) * 128 + r] = v.x;
            As[(k4l * 4 + 1) * 128 + r] = v.y;
            As[(k4l * 4 + 2) * 128 + r] = v.z;
            As[(k4l * 4 + 3) * 128 + r] = v.w;
        }
        // B panel: 32 k x 128 cols, direct float4 copy
        for (int f = tid; f < 1024; f += 256)
            ((float4*)Bs)[f] = ((const float4*)Ws)[kp * 1024 + f];
        __syncthreads();

        const float4* As4 = (const float4*)As;
        const float4* Bs4 = (const float4*)Bs;
#pragma unroll 8
        for (int k = 0; k < 32; k++) {
            float4 a0 = As4[k * 32 + ty * 2];
            float4 a1 = As4[k * 32 + ty * 2 + 1];
            float4 b0 = Bs4[k * 32 + tx * 2];
            float4 b1 = Bs4[k * 32 + tx * 2 + 1];
            float a[8] = {a0.x, a0.y, a0.z, a0.w, a1.x, a1.y, a1.z, a1.w};
            float b[8] = {b0.x, b0.y, b0.z, b0.w, b1.x, b1.y, b1.z, b1.w};
#pragma unroll
            for (int i = 0; i < 8; i++)
#pragma unroll
                for (int jj = 0; jj < 8; jj++)
                    acc[i][jj] += a[i] * b[jj];
        }
        __syncthreads();
    }

#pragma unroll
    for (int i = 0; i < 8; i++) {
        int r = row0 + ty * 8 + i;
        if (r < NN) {
            float4* dst = ((float4*)d_xlxr) + r * 64 + bn * 32 + tx * 2;
            dst[0] = make_float4(acc[i][0], acc[i][1], acc[i][2], acc[i][3]);
            dst[1] = make_float4(acc[i][4], acc[i][5], acc[i][6], acc[i][7]);
        }
    }
}

// ---------------- fused GATv2: online softmax + BN stats, warp/dst ---------
// grid 6250 x 256 threads (8 warps). Output: d_g + partial stats into psum/psq.
// Neighbor indices loaded coalesced per 32-chunk, distributed via shfl.
__global__ void k_gat(const float* __restrict__ att, const float* __restrict__ bias) {
    __shared__ float satt[128];
    __shared__ float sbias[64];
    __shared__ float sg[8][64];
    int tid = threadIdx.x;
    if (tid < 128) satt[tid] = att[tid];
    if (tid < 64) sbias[tid] = bias[tid];
    __syncthreads();

    int lane = tid & 31;
    int w = tid >> 5;
    int n = blockIdx.x * 8 + w;            // dst node (grid exactly covers NN)
    int row0 = d_rowptr[n], row1 = d_rowptr[n + 1];

    const float4* X4 = (const float4*)d_xlxr;
    float4 xr4 = X4[n * 64 + 32 + lane];
    float4 av  = ((const float4*)satt)[lane];

    float m = -1e30f, den = 0.f;
    float4 acc = make_float4(0.f, 0.f, 0.f, 0.f);

    for (int jb = row0; jb < row1; jb += 32) {
        int rem = row1 - jb;
        int cnt = rem < 32 ? rem : 32;
        int ld = lane < cnt ? lane : cnt - 1;
        int idx = d_csrc[jb + ld];          // coalesced chunk of neighbor ids

        int t = 0;
        for (; t + 1 < cnt; t += 2) {       // 2-edge unroll: two indep chains
            int s0 = __shfl_sync(0xffffffffu, idx, t);
            int s1 = __shfl_sync(0xffffffffu, idx, t + 1);
            float4 x0 = X4[s0 * 64 + lane];
            float4 x1 = X4[s1 * 64 + lane];
            float p0 = lrelu(x0.x + xr4.x) * av.x + lrelu(x0.y + xr4.y) * av.y +
                       lrelu(x0.z + xr4.z) * av.z + lrelu(x0.w + xr4.w) * av.w;
            float p1 = lrelu(x1.x + xr4.x) * av.x + lrelu(x1.y + xr4.y) * av.y +
                       lrelu(x1.z + xr4.z) * av.z + lrelu(x1.w + xr4.w) * av.w;
            p0 += __shfl_xor_sync(0xffffffffu, p0, 1);
            p1 += __shfl_xor_sync(0xffffffffu, p1, 1);
            p0 += __shfl_xor_sync(0xffffffffu, p0, 2);
            p1 += __shfl_xor_sync(0xffffffffu, p1, 2);
            p0 += __shfl_xor_sync(0xffffffffu, p0, 4);
            p1 += __shfl_xor_sync(0xffffffffu, p1, 4);
            p0 += __shfl_xor_sync(0xffffffffu, p0, 8);
            p1 += __shfl_xor_sync(0xffffffffu, p1, 8);

            float nm = fmaxf(m, fmaxf(p0, p1));
            float f  = __expf(m - nm);
            float e0 = __expf(p0 - nm);
            float e1 = __expf(p1 - nm);
            den = den * f + e0 + e1;
            acc.x = acc.x * f + e0 * x0.x + e1 * x1.x;
            acc.y = acc.y * f + e0 * x0.y + e1 * x1.y;
            acc.z = acc.z * f + e0 * x0.z + e1 * x1.z;
            acc.w = acc.w * f + e0 * x0.w + e1 * x1.w;
            m = nm;
        }
        if (t < cnt) {                      // tail edge of chunk
            int s0 = __shfl_sync(0xffffffffu, idx, t);
            float4 x0 = X4[s0 * 64 + lane];
            float p0 = lrelu(x0.x + xr4.x) * av.x + lrelu(x0.y + xr4.y) * av.y +
                       lrelu(x0.z + xr4.z) * av.z + lrelu(x0.w + xr4.w) * av.w;
            p0 += __shfl_xor_sync(0xffffffffu, p0, 1);
            p0 += __shfl_xor_sync(0xffffffffu, p0, 2);
            p0 += __shfl_xor_sync(0xffffffffu, p0, 4);
            p0 += __shfl_xor_sync(0xffffffffu, p0, 8);
            float nm = fmaxf(m, p0);
            float f  = __expf(m - nm);
            float e0 = __expf(p0 - nm);
            den = den * f + e0;
            acc.x = acc.x * f + e0 * x0.x;
            acc.y = acc.y * f + e0 * x0.y;
            acc.z = acc.z * f + e0 * x0.z;
            acc.w = acc.w * f + e0 * x0.w;
        }
    }

    float inv = 1.f / den;
    float4 r = make_float4(acc.x * inv, acc.y * inv, acc.z * inv, acc.w * inv);
    float ox = __shfl_xor_sync(0xffffffffu, r.x, 16);
    float oy = __shfl_xor_sync(0xffffffffu, r.y, 16);
    float oz = __shfl_xor_sync(0xffffffffu, r.z, 16);
    float ow = __shfl_xor_sync(0xffffffffu, r.w, 16);
    if (lane < 16) {
        float4 b4 = ((const float4*)sbias)[lane];
        float4 g;
        g.x = 0.5f * (r.x + ox) + b4.x;
        g.y = 0.5f * (r.y + oy) + b4.y;
        g.z = 0.5f * (r.z + oz) + b4.z;
        g.w = 0.5f * (r.w + ow) + b4.w;
        ((float4*)d_g)[n * 16 + lane] = g;
        sg[w][lane * 4 + 0] = g.x;
        sg[w][lane * 4 + 1] = g.y;
        sg[w][lane * 4 + 2] = g.z;
        sg[w][lane * 4 + 3] = g.w;
    }
    __syncthreads();
    if (tid < 64) {                        // per-block BN partial stats
        float s = 0.f, ss = 0.f;
#pragma unroll
        for (int q = 0; q < 8; q++) { float v = sg[q][tid]; s += v; ss += v * v; }
        int slot = (blockIdx.x & (GS - 1)) * HID + tid;
        atomicAdd(&d_psum[slot], (double)s);
        atomicAdd(&d_psq[slot], (double)ss);
    }
}

// -------- output head: fused BN+ELU+residual, then 64->32 ELU ->1 sigmoid --
__global__ void k_head(const float* __restrict__ W1, const float* __restrict__ b1,
                       const float* __restrict__ W2, const float* __restrict__ b2,
                       float* __restrict__ out) {
    __shared__ float W1s[64 * 32];
    __shared__ float b1s[32];
    __shared__ float W2s[32];
    __shared__ float scs[64], shs[64];
    int tid = threadIdx.x;
    for (int f = tid; f < 2048; f += 128) W1s[f] = W1[f];
    if (tid < 32) { b1s[tid] = b1[tid]; W2s[tid] = W2[tid]; }
    if (tid < 64) { scs[tid] = d_scale[tid]; shs[tid] = d_shift[tid]; }
    __syncthreads();
    int n = blockIdx.x * 128 + tid;
    if (n >= NN) return;
    float acc[32];
#pragma unroll
    for (int jj = 0; jj < 32; jj++) acc[jj] = b1s[jj];
    const float4* G4 = (const float4*)d_g;
    const float4* H4 = (const float4*)d_h1;   // h_11 lives in d_h1 (layer 11 write)
#pragma unroll 4
    for (int k4 = 0; k4 < 16; k4++) {
        float4 gg = G4[n * 16 + k4];
        float4 ho = H4[n * 16 + k4];
        float hv[4];
        hv[0] = eluf(fmaf(gg.x, scs[k4 * 4 + 0], shs[k4 * 4 + 0])) + ho.x;
        hv[1] = eluf(fmaf(gg.y, scs[k4 * 4 + 1], shs[k4 * 4 + 1])) + ho.y;
        hv[2] = eluf(fmaf(gg.z, scs[k4 * 4 + 2], shs[k4 * 4 + 2])) + ho.z;
        hv[3] = eluf(fmaf(gg.w, scs[k4 * 4 + 3], shs[k4 * 4 + 3])) + ho.w;
#pragma unroll
        for (int q = 0; q < 4; q++) {
            float xv = hv[q];
            int k = k4 * 4 + q;
#pragma unroll
            for (int jj = 0; jj < 32; jj++) acc[jj] += xv * W1s[k * 32 + jj];
        }
    }
    float o = b2[0];
#pragma unroll
    for (int jj = 0; jj < 32; jj++) o += eluf(acc[jj]) * W2s[jj];
    out[n] = 1.f / (1.f + expf(-o));
}

// ---------------- launcher -------------------------------------------------
extern "C" void kernel_launch(void* const* d_in, const int* in_sizes, int n_in,
                              void* d_out, int out_size) {
    const float* x        = (const float*)d_in[0];
    const int*   ei       = (const int*)  d_in[1];
    const float* in_W     = (const float*)d_in[2];
    const float* in_b     = (const float*)d_in[3];
    const float* in_gamma = (const float*)d_in[4];
    const float* in_beta  = (const float*)d_in[5];
    const float* Wl       = (const float*)d_in[6];
    const float* Wr       = (const float*)d_in[7];
    const float* att      = (const float*)d_in[8];
    const float* cbias    = (const float*)d_in[9];
    const float* bn_gamma = (const float*)d_in[10];
    const float* bn_beta  = (const float*)d_in[11];
    const float* out_W1   = (const float*)d_in[12];
    const float* out_b1   = (const float*)d_in[13];
    const float* out_W2   = (const float*)d_in[14];
    const float* out_b2   = (const float*)d_in[15];
    float* out = (float*)d_out;

    dim3 tb64_4(64, 4);
    dim3 gemm_grid((NN + 127) / 128, 2);

    // launch index 3 = layer-0 GEMM (ncu profiles launch #3)
    k_in_proj<<<GS, tb64_4>>>(x, in_W, in_b);                 // 0
    k_bn_prep<<<1, HID>>>(in_gamma, in_beta);                 // 1
    k_zero_deg<<<(NN + 255) / 256, 256>>>();                  // 2
    k_gemm<<<gemm_grid, 256>>>(Wl, Wr, 0);                    // 3 <- profiled

    // CSR build (once per launch, reused by all 12 layers)
    k_count<<<(ENT + 255) / 256, 256>>>(ei);
    k_scan1<<<SCAN_NB, SCAN_BLK>>>();
    k_scan2<<<1, 1>>>();
    k_scan3<<<SCAN_NB, SCAN_BLK>>>();
    k_scatter<<<(ENT + 255) / 256, 256>>>(ei);

    k_gat<<<NN / 8, 256>>>(att, cbias);
    k_bn_prep<<<1, HID>>>(bn_gamma, bn_beta);

    for (int i = 1; i < 12; i++) {
        k_gemm<<<gemm_grid, 256>>>(Wl + i * HID * 128, Wr + i * HID * 128, i);
        k_gat<<<NN / 8, 256>>>(att + i * 128, cbias + i * HID);
        k_bn_prep<<<1, HID>>>(bn_gamma + i * HID, bn_beta + i * HID);
    }

    k_head<<<(NN + 127) / 128, 128>>>(out_W1, out_b1, out_W2, out_b2, out);
}

// round 14
// speedup vs baseline: 1.0037x; 1.0037x over previous
#include <cuda_runtime.h>
#include <math.h>

#define NN   50000
#define FIN  17
#define HID  64
#define EE   400000
#define ENT  450000   // EE + NN self loops
#define GS   128      // BN partial-sum slots
#define SCAN_BLK 512
#define SCAN_NB  98   // ceil(NN/512)

// ---------------- scratch (static __device__, no allocation) ----------------
__device__ __align__(16) float d_h0[NN * HID];   // node features (ping)
__device__ __align__(16) float d_h1[NN * HID];   // node features (pong)
__device__ __align__(16) float d_g[NN * HID];    // pre-BN buffer
__device__ __align__(16) float d_xlxr[NN * 256]; // [xl(128) | xr(128)] per node
__device__ double d_psum[GS * HID];              // BN partial sums (atomic slots)
__device__ double d_psq[GS * HID];               // BN partial sums of squares
__device__ __align__(16) float d_scale[HID];     // folded BN scale
__device__ __align__(16) float d_shift[HID];     // folded BN shift
__device__ int    d_deg[NN];
__device__ int    d_rowptr[NN + 1];
__device__ int    d_cursor[NN];
__device__ int    d_csrc[ENT];
__device__ int    d_bsum[SCAN_NB];

__device__ __forceinline__ float eluf(float v)  { return v > 0.f ? v : expm1f(v); }
__device__ __forceinline__ float lrelu(float v) { return v > 0.f ? v : 0.2f * v; }

// ================= CSR build =================
__global__ void k_zero_deg() {
    int i = blockIdx.x * blockDim.x + threadIdx.x;
    if (i < NN) d_deg[i] = 0;
}
__global__ void k_count(const int* __restrict__ ei) {
    int i = blockIdx.x * blockDim.x + threadIdx.x;
    if (i >= ENT) return;
    int dst = (i < EE) ? ei[EE + i] : (i - EE);
    atomicAdd(&d_deg[dst], 1);
}
__global__ void k_scan1() {
    __shared__ int sm[SCAN_BLK];
    int i = blockIdx.x * SCAN_BLK + threadIdx.x;
    sm[threadIdx.x] = (i < NN) ? d_deg[i] : 0;
    __syncthreads();
    for (int o = SCAN_BLK / 2; o; o >>= 1) {
        if (threadIdx.x < o) sm[threadIdx.x] += sm[threadIdx.x + o];
        __syncthreads();
    }
    if (threadIdx.x == 0) d_bsum[blockIdx.x] = sm[0];
}
__global__ void k_scan2() {
    int acc = 0;
    for (int b = 0; b < SCAN_NB; b++) { int t = d_bsum[b]; d_bsum[b] = acc; acc += t; }
}
__global__ void k_scan3() {
    __shared__ int sm[SCAN_BLK];
    int i = blockIdx.x * SCAN_BLK + threadIdx.x;
    int v = (i < NN) ? d_deg[i] : 0;
    sm[threadIdx.x] = v;
    __syncthreads();
    for (int o = 1; o < SCAN_BLK; o <<= 1) {
        int t = (threadIdx.x >= o) ? sm[threadIdx.x - o] : 0;
        __syncthreads();
        sm[threadIdx.x] += t;
        __syncthreads();
    }
    int excl = sm[threadIdx.x] - v + d_bsum[blockIdx.x];
    if (i < NN) {
        d_rowptr[i] = excl;
        d_cursor[i] = excl;
        if (i == NN - 1) d_rowptr[NN] = excl + v;
    }
}
__global__ void k_scatter(const int* __restrict__ ei) {
    int i = blockIdx.x * blockDim.x + threadIdx.x;
    if (i >= ENT) return;
    int src, dst;
    if (i < EE) { src = ei[i]; dst = ei[EE + i]; } else { src = i - EE; dst = src; }
    int pos = atomicAdd(&d_cursor[dst], 1);
    d_csrc[pos] = src;
}

// ---------------- input projection + BN stats. blockDim (64,4), grid GS ----
__global__ void k_in_proj(const float* __restrict__ x,
                          const float* __restrict__ W,
                          const float* __restrict__ b) {
    int c = threadIdx.x, ty = threadIdx.y;
    float wcol[FIN];
#pragma unroll
    for (int k = 0; k < FIN; k++) wcol[k] = W[k * HID + c];
    float bias = b[c];
    double s = 0.0, ss = 0.0;
    for (int n = blockIdx.x * 4 + ty; n < NN; n += GS * 4) {
        const float* xr = x + n * FIN;
        float acc = bias;
#pragma unroll
        for (int k = 0; k < FIN; k++) acc += xr[k] * wcol[k];
        d_g[n * HID + c] = acc;
        s += acc; ss += (double)acc * acc;
    }
    __shared__ double sm[4][HID], sm2[4][HID];
    sm[ty][c] = s; sm2[ty][c] = ss;
    __syncthreads();
    if (ty == 0) {
        d_psum[blockIdx.x * HID + c] = sm[0][c] + sm[1][c] + sm[2][c] + sm[3][c];
        d_psq [blockIdx.x * HID + c] = sm2[0][c] + sm2[1][c] + sm2[2][c] + sm2[3][c];
    }
}

// ---- fold BN into scale/shift, then zero the accumulator slots. 1x64 ------
__global__ void k_bn_prep(const float* __restrict__ gamma,
                          const float* __restrict__ beta) {
    int c = threadIdx.x;
    double s = 0.0, ss = 0.0;
    for (int i = 0; i < GS; i++) { s += d_psum[i * HID + c]; ss += d_psq[i * HID + c]; }
    double m   = s / (double)NN;
    double var = ss / (double)NN - m * m;
    double rs  = 1.0 / sqrt(var + 1e-5);
    double g   = (double)gamma[c] * rs;
    d_scale[c] = (float)g;
    d_shift[c] = (float)((double)beta[c] - m * g);
    for (int i = 0; i < GS; i++) { d_psum[i * HID + c] = 0.0; d_psq[i * HID + c] = 0.0; }
}

// ---------------- GEMM with fused BN-apply + ELU + residual ----------------
// A = h_layer = elu(g*scale+shift) (+ h_old). blockIdx.y==0 also writes h out.
// 256 threads, tile 128(rows) x 128(cols), K in 2 panels of 32. grid (391, 2).
// Microtile 8x8 -> 4 LDS.128 per 64 FFMA (FFMA-issue bound).
__global__ void __launch_bounds__(256, 2)
k_gemm(const float* __restrict__ Wlp, const float* __restrict__ Wrp, int layer) {
    __shared__ float As[32 * 128];   // K-panel major: As[k][r]
    __shared__ float Bs[32 * 128];   // Bs[k][j]
    int tid = threadIdx.x;
    int bn = blockIdx.y;             // 0 -> Wl, 1 -> Wr
    int row0 = blockIdx.x * 128;

    const float4* G4  = (const float4*)d_g;
    const float4* HO4 = (layer & 1) ? (const float4*)d_h0 : (const float4*)d_h1;
    float4*       HW4 = (layer & 1) ? (float4*)d_h1 : (float4*)d_h0;
    int  res = (layer > 0);
    bool wr  = (bn == 0);
    const float* Ws = bn ? Wrp : Wlp;

    int tx = tid & 15, ty = tid >> 4;      // 16 col-groups x 16 row-groups
    float acc[8][8] = {};

    for (int kp = 0; kp < 2; kp++) {
        // A panel: 128 rows x 32 k; BN+ELU(+residual) applied on the fly
        for (int f = tid; f < 1024; f += 256) {
            int r = f & 127, k4l = f >> 7;          // k4l 0..7
            int k4 = kp * 8 + k4l;
            float4 v = make_float4(0.f, 0.f, 0.f, 0.f);
            int row = row0 + r;
            if (row < NN) {
                float4 gg = G4[row * 16 + k4];
                float4 sc = ((const float4*)d_scale)[k4];
                float4 sh = ((const float4*)d_shift)[k4];
                v.x = eluf(fmaf(gg.x, sc.x, sh.x));
                v.y = eluf(fmaf(gg.y, sc.y, sh.y));
                v.z = eluf(fmaf(gg.z, sc.z, sh.z));
                v.w = eluf(fmaf(gg.w, sc.w, sh.w));
                if (res) {
                    float4 ho = HO4[row * 16 + k4];
                    v.x += ho.x; v.y += ho.y; v.z += ho.z; v.w += ho.w;
                }
                if (wr) HW4[row * 16 + k4] = v;
            }
            As[(k4l * 4 + 0) * 128 + r] = v.x;
            As[(k4l * 4 + 1) * 128 + r] = v.y;
            As[(k4l * 4 + 2) * 128 + r] = v.z;
            As[(k4l * 4 + 3) * 128 + r] = v.w;
        }
        // B panel: 32 k x 128 cols, direct float4 copy
        for (int f = tid; f < 1024; f += 256)
            ((float4*)Bs)[f] = ((const float4*)Ws)[kp * 1024 + f];
        __syncthreads();

        const float4* As4 = (const float4*)As;
        const float4* Bs4 = (const float4*)Bs;
#pragma unroll 8
        for (int k = 0; k < 32; k++) {
            float4 a0 = As4[k * 32 + ty * 2];
            float4 a1 = As4[k * 32 + ty * 2 + 1];
            float4 b0 = Bs4[k * 32 + tx * 2];
            float4 b1 = Bs4[k * 32 + tx * 2 + 1];
            float a[8] = {a0.x, a0.y, a0.z, a0.w, a1.x, a1.y, a1.z, a1.w};
            float b[8] = {b0.x, b0.y, b0.z, b0.w, b1.x, b1.y, b1.z, b1.w};
#pragma unroll
            for (int i = 0; i < 8; i++)
#pragma unroll
                for (int jj = 0; jj < 8; jj++)
                    acc[i][jj] += a[i] * b[jj];
        }
        __syncthreads();
    }

#pragma unroll
    for (int i = 0; i < 8; i++) {
        int r = row0 + ty * 8 + i;
        if (r < NN) {
            float4* dst = ((float4*)d_xlxr) + r * 64 + bn * 32 + tx * 2;
            dst[0] = make_float4(acc[i][0], acc[i][1], acc[i][2], acc[i][3]);
            dst[1] = make_float4(acc[i][4], acc[i][5], acc[i][6], acc[i][7]);
        }
    }
}

// ---------------- fused GATv2: online softmax + BN stats, warp/dst ---------
// grid 6250 x 256 threads (8 warps). Output: d_g + partial stats into psum/psq.
// Neighbor indices loaded coalesced per 32-chunk, distributed via shfl.
__global__ void k_gat(const float* __restrict__ att, const float* __restrict__ bias) {
    __shared__ float satt[128];
    __shared__ float sbias[64];
    __shared__ float sg[8][64];
    int tid = threadIdx.x;
    if (tid < 128) satt[tid] = att[tid];
    if (tid < 64) sbias[tid] = bias[tid];
    __syncthreads();

    int lane = tid & 31;
    int w = tid >> 5;
    int n = blockIdx.x * 8 + w;            // dst node (grid exactly covers NN)
    int row0 = d_rowptr[n], row1 = d_rowptr[n + 1];

    const float4* X4 = (const float4*)d_xlxr;
    float4 xr4 = X4[n * 64 + 32 + lane];
    float4 av  = ((const float4*)satt)[lane];

    float m = -1e30f, den = 0.f;
    float4 acc = make_float4(0.f, 0.f, 0.f, 0.f);

    for (int jb = row0; jb < row1; jb += 32) {
        int rem = row1 - jb;
        int cnt = rem < 32 ? rem : 32;
        int ld = lane < cnt ? lane : cnt - 1;
        int idx = d_csrc[jb + ld];          // coalesced chunk of neighbor ids

        int t = 0;
        for (; t + 1 < cnt; t += 2) {       // 2-edge unroll: two indep chains
            int s0 = __shfl_sync(0xffffffffu, idx, t);
            int s1 = __shfl_sync(0xffffffffu, idx, t + 1);
            float4 x0 = X4[s0 * 64 + lane];
            float4 x1 = X4[s1 * 64 + lane];
            float p0 = lrelu(x0.x + xr4.x) * av.x + lrelu(x0.y + xr4.y) * av.y +
                       lrelu(x0.z + xr4.z) * av.z + lrelu(x0.w + xr4.w) * av.w;
            float p1 = lrelu(x1.x + xr4.x) * av.x + lrelu(x1.y + xr4.y) * av.y +
                       lrelu(x1.z + xr4.z) * av.z + lrelu(x1.w + xr4.w) * av.w;
            p0 += __shfl_xor_sync(0xffffffffu, p0, 1);
            p1 += __shfl_xor_sync(0xffffffffu, p1, 1);
            p0 += __shfl_xor_sync(0xffffffffu, p0, 2);
            p1 += __shfl_xor_sync(0xffffffffu, p1, 2);
            p0 += __shfl_xor_sync(0xffffffffu, p0, 4);
            p1 += __shfl_xor_sync(0xffffffffu, p1, 4);
            p0 += __shfl_xor_sync(0xffffffffu, p0, 8);
            p1 += __shfl_xor_sync(0xffffffffu, p1, 8);

            float nm = fmaxf(m, fmaxf(p0, p1));
            float f  = __expf(m - nm);
            float e0 = __expf(p0 - nm);
            float e1 = __expf(p1 - nm);
            den = den * f + e0 + e1;
            acc.x = acc.x * f + e0 * x0.x + e1 * x1.x;
            acc.y = acc.y * f + e0 * x0.y + e1 * x1.y;
            acc.z = acc.z * f + e0 * x0.z + e1 * x1.z;
            acc.w = acc.w * f + e0 * x0.w + e1 * x1.w;
            m = nm;
        }
        if (t < cnt) {                      // tail edge of chunk
            int s0 = __shfl_sync(0xffffffffu, idx, t);
            float4 x0 = X4[s0 * 64 + lane];
            float p0 = lrelu(x0.x + xr4.x) * av.x + lrelu(x0.y + xr4.y) * av.y +
                       lrelu(x0.z + xr4.z) * av.z + lrelu(x0.w + xr4.w) * av.w;
            p0 += __shfl_xor_sync(0xffffffffu, p0, 1);
            p0 += __shfl_xor_sync(0xffffffffu, p0, 2);
            p0 += __shfl_xor_sync(0xffffffffu, p0, 4);
            p0 += __shfl_xor_sync(0xffffffffu, p0, 8);
            float nm = fmaxf(m, p0);
            float f  = __expf(m - nm);
            float e0 = __expf(p0 - nm);
            den = den * f + e0;
            acc.x = acc.x * f + e0 * x0.x;
            acc.y = acc.y * f + e0 * x0.y;
            acc.z = acc.z * f + e0 * x0.z;
            acc.w = acc.w * f + e0 * x0.w;
        }
    }

    float inv = 1.f / den;
    float4 r = make_float4(acc.x * inv, acc.y * inv, acc.z * inv, acc.w * inv);
    float ox = __shfl_xor_sync(0xffffffffu, r.x, 16);
    float oy = __shfl_xor_sync(0xffffffffu, r.y, 16);
    float oz = __shfl_xor_sync(0xffffffffu, r.z, 16);
    float ow = __shfl_xor_sync(0xffffffffu, r.w, 16);
    if (lane < 16) {
        float4 b4 = ((const float4*)sbias)[lane];
        float4 g;
        g.x = 0.5f * (r.x + ox) + b4.x;
        g.y = 0.5f * (r.y + oy) + b4.y;
        g.z = 0.5f * (r.z + oz) + b4.z;
        g.w = 0.5f * (r.w + ow) + b4.w;
        ((float4*)d_g)[n * 16 + lane] = g;
        sg[w][lane * 4 + 0] = g.x;
        sg[w][lane * 4 + 1] = g.y;
        sg[w][lane * 4 + 2] = g.z;
        sg[w][lane * 4 + 3] = g.w;
    }
    __syncthreads();
    if (tid < 64) {                        // per-block BN partial stats
        float s = 0.f, ss = 0.f;
#pragma unroll
        for (int q = 0; q < 8; q++) { float v = sg[q][tid]; s += v; ss += v * v; }
        int slot = (blockIdx.x & (GS - 1)) * HID + tid;
        atomicAdd(&d_psum[slot], (double)s);
        atomicAdd(&d_psq[slot], (double)ss);
    }
}

// -------- output head: fused BN+ELU+residual, then 64->32 ELU ->1 sigmoid --
__global__ void k_head(const float* __restrict__ W1, const float* __restrict__ b1,
                       const float* __restrict__ W2, const float* __restrict__ b2,
                       float* __restrict__ out) {
    __shared__ float W1s[64 * 32];
    __shared__ float b1s[32];
    __shared__ float W2s[32];
    __shared__ float scs[64], shs[64];
    int tid = threadIdx.x;
    for (int f = tid; f < 2048; f += 128) W1s[f] = W1[f];
    if (tid < 32) { b1s[tid] = b1[tid]; W2s[tid] = W2[tid]; }
    if (tid < 64) { scs[tid] = d_scale[tid]; shs[tid] = d_shift[tid]; }
    __syncthreads();
    int n = blockIdx.x * 128 + tid;
    if (n >= NN) return;
    float acc[32];
#pragma unroll
    for (int jj = 0; jj < 32; jj++) acc[jj] = b1s[jj];
    const float4* G4 = (const float4*)d_g;
    const float4* H4 = (const float4*)d_h1;   // h_11 lives in d_h1 (layer 11 write)
#pragma unroll 4
    for (int k4 = 0; k4 < 16; k4++) {
        float4 gg = G4[n * 16 + k4];
        float4 ho = H4[n * 16 + k4];
        float hv[4];
        hv[0] = eluf(fmaf(gg.x, scs[k4 * 4 + 0], shs[k4 * 4 + 0])) + ho.x;
        hv[1] = eluf(fmaf(gg.y, scs[k4 * 4 + 1], shs[k4 * 4 + 1])) + ho.y;
        hv[2] = eluf(fmaf(gg.z, scs[k4 * 4 + 2], shs[k4 * 4 + 2])) + ho.z;
        hv[3] = eluf(fmaf(gg.w, scs[k4 * 4 + 3], shs[k4 * 4 + 3])) + ho.w;
#pragma unroll
        for (int q = 0; q < 4; q++) {
            float xv = hv[q];
            int k = k4 * 4 + q;
#pragma unroll
            for (int jj = 0; jj < 32; jj++) acc[jj] += xv * W1s[k * 32 + jj];
        }
    }
    float o = b2[0];
#pragma unroll
    for (int jj = 0; jj < 32; jj++) o += eluf(acc[jj]) * W2s[jj];
    out[n] = 1.f / (1.f + expf(-o));
}

// ---------------- launcher -------------------------------------------------
extern "C" void kernel_launch(void* const* d_in, const int* in_sizes, int n_in,
                              void* d_out, int out_size) {
    const float* x        = (const float*)d_in[0];
    const int*   ei       = (const int*)  d_in[1];
    const float* in_W     = (const float*)d_in[2];
    const float* in_b     = (const float*)d_in[3];
    const float* in_gamma = (const float*)d_in[4];
    const float* in_beta  = (const float*)d_in[5];
    const float* Wl       = (const float*)d_in[6];
    const float* Wr       = (const float*)d_in[7];
    const float* att      = (const float*)d_in[8];
    const float* cbias    = (const float*)d_in[9];
    const float* bn_gamma = (const float*)d_in[10];
    const float* bn_beta  = (const float*)d_in[11];
    const float* out_W1   = (const float*)d_in[12];
    const float* out_b1   = (const float*)d_in[13];
    const float* out_W2   = (const float*)d_in[14];
    const float* out_b2   = (const float*)d_in[15];
    float* out = (float*)d_out;

    dim3 tb64_4(64, 4);
    dim3 gemm_grid((NN + 127) / 128, 2);

    // launch index 3 = layer-0 GEMM (ncu profiles launch #3)
    k_in_proj<<<GS, tb64_4>>>(x, in_W, in_b);                 // 0
    k_bn_prep<<<1, HID>>>(in_gamma, in_beta);                 // 1
    k_zero_deg<<<(NN + 255) / 256, 256>>>();                  // 2
    k_gemm<<<gemm_grid, 256>>>(Wl, Wr, 0);                    // 3 <- profiled

    // CSR build (once per launch, reused by all 12 layers)
    k_count<<<(ENT + 255) / 256, 256>>>(ei);
    k_scan1<<<SCAN_NB, SCAN_BLK>>>();
    k_scan2<<<1, 1>>>();
    k_scan3<<<SCAN_NB, SCAN_BLK>>>();
    k_scatter<<<(ENT + 255) / 256, 256>>>(ei);

    k_gat<<<NN / 8, 256>>>(att, cbias);
    k_bn_prep<<<1, HID>>>(bn_gamma, bn_beta);

    for (int i = 1; i < 12; i++) {
        k_gemm<<<gemm_grid, 256>>>(Wl + i * HID * 128, Wr + i * HID * 128, i);
        k_gat<<<NN / 8, 256>>>(att + i * 128, cbias + i * HID);
        k_bn_prep<<<1, HID>>>(bn_gamma + i * HID, bn_beta + i * HID);
    }

    k_head<<<(NN + 127) / 128, 128>>>(out_W1, out_b1, out_W2, out_b2, out);
}

// round 15
// speedup vs baseline: 1.0884x; 1.0844x over previous
#include <cuda_runtime.h>
#include <math.h>

#define NN   50000
#define FIN  17
#define HID  64
#define EE   400000
#define ENT  450000   // EE + NN self loops
#define GS   128      // BN partial-sum slots
#define SCAN_BLK 512
#define SCAN_NB  98   // ceil(NN/512)

// ---------------- scratch (static __device__, no allocation) ----------------
__device__ __align__(16) float d_h0[NN * HID];   // node features (ping)
__device__ __align__(16) float d_h1[NN * HID];   // node features (pong)
__device__ __align__(16) float d_g[NN * HID];    // pre-BN buffer
__device__ __align__(16) float d_xlxr[NN * 256]; // [xl(128) | xr(128)] per node
__device__ double d_psum[GS * HID];              // BN partial sums (atomic slots)
__device__ double d_psq[GS * HID];               // BN partial sums of squares
__device__ __align__(16) float d_scale[HID];     // folded BN scale
__device__ __align__(16) float d_shift[HID];     // folded BN shift
__device__ int    d_deg[NN];
__device__ int    d_rowptr[NN + 1];
__device__ int    d_cursor[NN];
__device__ int    d_csrc[ENT];
__device__ int    d_bsum[SCAN_NB];

__device__ __forceinline__ float eluf(float v)  { return v > 0.f ? v : expm1f(v); }
__device__ __forceinline__ float lrelu(float v) { return v > 0.f ? v : 0.2f * v; }

// ================= CSR build =================
__global__ void k_zero_deg() {
    int i = blockIdx.x * blockDim.x + threadIdx.x;
    if (i < NN) d_deg[i] = 0;
}
__global__ void k_count(const int* __restrict__ ei) {
    int i = blockIdx.x * blockDim.x + threadIdx.x;
    if (i >= ENT) return;
    int dst = (i < EE) ? ei[EE + i] : (i - EE);
    atomicAdd(&d_deg[dst], 1);
}
__global__ void k_scan1() {
    __shared__ int sm[SCAN_BLK];
    int i = blockIdx.x * SCAN_BLK + threadIdx.x;
    sm[threadIdx.x] = (i < NN) ? d_deg[i] : 0;
    __syncthreads();
    for (int o = SCAN_BLK / 2; o; o >>= 1) {
        if (threadIdx.x < o) sm[threadIdx.x] += sm[threadIdx.x + o];
        __syncthreads();
    }
    if (threadIdx.x == 0) d_bsum[blockIdx.x] = sm[0];
}
__global__ void k_scan2() {
    int acc = 0;
    for (int b = 0; b < SCAN_NB; b++) { int t = d_bsum[b]; d_bsum[b] = acc; acc += t; }
}
__global__ void k_scan3() {
    __shared__ int sm[SCAN_BLK];
    int i = blockIdx.x * SCAN_BLK + threadIdx.x;
    int v = (i < NN) ? d_deg[i] : 0;
    sm[threadIdx.x] = v;
    __syncthreads();
    for (int o = 1; o < SCAN_BLK; o <<= 1) {
        int t = (threadIdx.x >= o) ? sm[threadIdx.x - o] : 0;
        __syncthreads();
        sm[threadIdx.x] += t;
        __syncthreads();
    }
    int excl = sm[threadIdx.x] - v + d_bsum[blockIdx.x];
    if (i < NN) {
        d_rowptr[i] = excl;
        d_cursor[i] = excl;
        if (i == NN - 1) d_rowptr[NN] = excl + v;
    }
}
__global__ void k_scatter(const int* __restrict__ ei) {
    int i = blockIdx.x * blockDim.x + threadIdx.x;
    if (i >= ENT) return;
    int src, dst;
    if (i < EE) { src = ei[i]; dst = ei[EE + i]; } else { src = i - EE; dst = src; }
    int pos = atomicAdd(&d_cursor[dst], 1);
    d_csrc[pos] = src;
}

// ---------------- input projection + BN stats. blockDim (64,4), grid GS ----
__global__ void k_in_proj(const float* __restrict__ x,
                          const float* __restrict__ W,
                          const float* __restrict__ b) {
    int c = threadIdx.x, ty = threadIdx.y;
    float wcol[FIN];
#pragma unroll
    for (int k = 0; k < FIN; k++) wcol[k] = W[k * HID + c];
    float bias = b[c];
    double s = 0.0, ss = 0.0;
    for (int n = blockIdx.x * 4 + ty; n < NN; n += GS * 4) {
        const float* xr = x + n * FIN;
        float acc = bias;
#pragma unroll
        for (int k = 0; k < FIN; k++) acc += xr[k] * wcol[k];
        d_g[n * HID + c] = acc;
        s += acc; ss += (double)acc * acc;
    }
    __shared__ double sm[4][HID], sm2[4][HID];
    sm[ty][c] = s; sm2[ty][c] = ss;
    __syncthreads();
    if (ty == 0) {
        d_psum[blockIdx.x * HID + c] = sm[0][c] + sm[1][c] + sm[2][c] + sm[3][c];
        d_psq [blockIdx.x * HID + c] = sm2[0][c] + sm2[1][c] + sm2[2][c] + sm2[3][c];
    }
}

// ---- fold BN into scale/shift + zero slots. blockDim (64,8), 1 block ------
__global__ void k_bn_prep(const float* __restrict__ gamma,
                          const float* __restrict__ beta) {
    int c = threadIdx.x, ty = threadIdx.y;
    __shared__ double sm[8][HID], sm2[8][HID];
    double s = 0.0, ss = 0.0;
#pragma unroll
    for (int q = 0; q < 16; q++) {
        int i = ty * 16 + q;
        s  += d_psum[i * HID + c];
        ss += d_psq[i * HID + c];
        d_psum[i * HID + c] = 0.0;
        d_psq[i * HID + c]  = 0.0;
    }
    sm[ty][c] = s; sm2[ty][c] = ss;
    __syncthreads();
    if (ty == 0) {
        double S = 0.0, SS = 0.0;
#pragma unroll
        for (int q = 0; q < 8; q++) { S += sm[q][c]; SS += sm2[q][c]; }
        double m   = S / (double)NN;
        double var = SS / (double)NN - m * m;
        double rs  = 1.0 / sqrt(var + 1e-5);
        double g   = (double)gamma[c] * rs;
        d_scale[c] = (float)g;
        d_shift[c] = (float)((double)beta[c] - m * g);
    }
}

// ---------------- GEMM with fused BN-apply + ELU + residual ----------------
// R12 configuration: 256 threads, tile 128(rows) x 64(cols), K=64, 8x4 micro.
// grid (391, 4). A = h_layer = elu(g*scale+shift) (+ h_old); bn==0 writes h.
__global__ void k_gemm(const float* __restrict__ Wlp,
                       const float* __restrict__ Wrp, int layer) {
    __shared__ float As[64 * 128];   // K-major: As[k][r]
    __shared__ float Bs[64 * 64];    // Bs[k][j]
    int tid = threadIdx.x;
    int bn = blockIdx.y;
    int row0 = blockIdx.x * 128;

    const float4* G4  = (const float4*)d_g;
    const float4* HO4 = (layer & 1) ? (const float4*)d_h0 : (const float4*)d_h1;
    float4*       HW4 = (layer & 1) ? (float4*)d_h1 : (float4*)d_h0;
    int  res = (layer > 0);
    bool wr  = (bn == 0);

    // A tile: 128 rows x 64 k; apply BN+ELU(+residual) on the fly
    for (int f = tid; f < 2048; f += 256) {
        int r = f & 127, k4 = f >> 7;
        float4 v = make_float4(0.f, 0.f, 0.f, 0.f);
        int row = row0 + r;
        if (row < NN) {
            float4 gg = G4[row * 16 + k4];
            float4 sc = ((const float4*)d_scale)[k4];
            float4 sh = ((const float4*)d_shift)[k4];
            v.x = eluf(fmaf(gg.x, sc.x, sh.x));
            v.y = eluf(fmaf(gg.y, sc.y, sh.y));
            v.z = eluf(fmaf(gg.z, sc.z, sh.z));
            v.w = eluf(fmaf(gg.w, sc.w, sh.w));
            if (res) {
                float4 ho = HO4[row * 16 + k4];
                v.x += ho.x; v.y += ho.y; v.z += ho.z; v.w += ho.w;
            }
            if (wr) HW4[row * 16 + k4] = v;
        }
        As[(k4 * 4 + 0) * 128 + r] = v.x;
        As[(k4 * 4 + 1) * 128 + r] = v.y;
        As[(k4 * 4 + 2) * 128 + r] = v.z;
        As[(k4 * 4 + 3) * 128 + r] = v.w;
    }
    // B tile: 64 k x 64 cols from [Wl|Wr]
    const float* Ws = (bn < 2) ? Wlp : Wrp;
    int coff4 = (bn & 1) * 16;
    for (int f = tid; f < 1024; f += 256) {
        int k = f >> 4, j4 = f & 15;
        ((float4*)Bs)[k * 16 + j4] = ((const float4*)Ws)[k * 32 + coff4 + j4];
    }
    __syncthreads();

    int tx = tid & 15, ty = tid >> 4;     // 8 rows x 4 cols per thread
    const float4* As4 = (const float4*)As;
    const float4* Bs4 = (const float4*)Bs;
    float acc[8][4] = {};
#pragma unroll 8
    for (int k = 0; k < 64; k++) {
        float4 b4 = Bs4[k * 16 + tx];
        float4 a0 = As4[k * 32 + ty * 2];
        float4 a1 = As4[k * 32 + ty * 2 + 1];
        float a[8] = {a0.x, a0.y, a0.z, a0.w, a1.x, a1.y, a1.z, a1.w};
#pragma unroll
        for (int i = 0; i < 8; i++) {
            acc[i][0] += a[i] * b4.x;
            acc[i][1] += a[i] * b4.y;
            acc[i][2] += a[i] * b4.z;
            acc[i][3] += a[i] * b4.w;
        }
    }
#pragma unroll
    for (int i = 0; i < 8; i++) {
        int r = row0 + ty * 8 + i;
        if (r < NN)
            ((float4*)d_xlxr)[r * 64 + bn * 16 + tx] =
                make_float4(acc[i][0], acc[i][1], acc[i][2], acc[i][3]);
    }
}

// ---------------- fused GATv2: online softmax + BN stats, warp/dst ---------
// grid 6250 x 256 threads (8 warps). 4-edge unroll per softmax update.
__global__ void k_gat(const float* __restrict__ att, const float* __restrict__ bias) {
    __shared__ float satt[128];
    __shared__ float sbias[64];
    __shared__ float sg[8][64];
    int tid = threadIdx.x;
    if (tid < 128) satt[tid] = att[tid];
    if (tid < 64) sbias[tid] = bias[tid];
    __syncthreads();

    int lane = tid & 31;
    int w = tid >> 5;
    int n = blockIdx.x * 8 + w;            // dst node (grid exactly covers NN)
    int row0 = d_rowptr[n], row1 = d_rowptr[n + 1];

    const float4* X4 = (const float4*)d_xlxr;
    float4 xr4 = X4[n * 64 + 32 + lane];
    float4 av  = ((const float4*)satt)[lane];

    float m = -1e30f, den = 0.f;
    float4 acc = make_float4(0.f, 0.f, 0.f, 0.f);

    for (int jb = row0; jb < row1; jb += 32) {
        int rem = row1 - jb;
        int cnt = rem < 32 ? rem : 32;
        int ld = lane < cnt ? lane : cnt - 1;
        int idx = d_csrc[jb + ld];          // coalesced chunk of neighbor ids

        int t = 0;
        for (; t + 3 < cnt; t += 4) {       // 4-edge unroll
            int s0 = __shfl_sync(0xffffffffu, idx, t);
            int s1 = __shfl_sync(0xffffffffu, idx, t + 1);
            int s2 = __shfl_sync(0xffffffffu, idx, t + 2);
            int s3 = __shfl_sync(0xffffffffu, idx, t + 3);
            float4 x0 = X4[s0 * 64 + lane];
            float4 x1 = X4[s1 * 64 + lane];
            float4 x2 = X4[s2 * 64 + lane];
            float4 x3 = X4[s3 * 64 + lane];
            float p0 = lrelu(x0.x + xr4.x) * av.x + lrelu(x0.y + xr4.y) * av.y +
                       lrelu(x0.z + xr4.z) * av.z + lrelu(x0.w + xr4.w) * av.w;
            float p1 = lrelu(x1.x + xr4.x) * av.x + lrelu(x1.y + xr4.y) * av.y +
                       lrelu(x1.z + xr4.z) * av.z + lrelu(x1.w + xr4.w) * av.w;
            float p2 = lrelu(x2.x + xr4.x) * av.x + lrelu(x2.y + xr4.y) * av.y +
                       lrelu(x2.z + xr4.z) * av.z + lrelu(x2.w + xr4.w) * av.w;
            float p3 = lrelu(x3.x + xr4.x) * av.x + lrelu(x3.y + xr4.y) * av.y +
                       lrelu(x3.z + xr4.z) * av.z + lrelu(x3.w + xr4.w) * av.w;
            // interleaved butterfly reductions (16 shfls, pipelined)
            p0 += __shfl_xor_sync(0xffffffffu, p0, 1);
            p1 += __shfl_xor_sync(0xffffffffu, p1, 1);
            p2 += __shfl_xor_sync(0xffffffffu, p2, 1);
            p3 += __shfl_xor_sync(0xffffffffu, p3, 1);
            p0 += __shfl_xor_sync(0xffffffffu, p0, 2);
            p1 += __shfl_xor_sync(0xffffffffu, p1, 2);
            p2 += __shfl_xor_sync(0xffffffffu, p2, 2);
            p3 += __shfl_xor_sync(0xffffffffu, p3, 2);
            p0 += __shfl_xor_sync(0xffffffffu, p0, 4);
            p1 += __shfl_xor_sync(0xffffffffu, p1, 4);
            p2 += __shfl_xor_sync(0xffffffffu, p2, 4);
            p3 += __shfl_xor_sync(0xffffffffu, p3, 4);
            p0 += __shfl_xor_sync(0xffffffffu, p0, 8);
            p1 += __shfl_xor_sync(0xffffffffu, p1, 8);
            p2 += __shfl_xor_sync(0xffffffffu, p2, 8);
            p3 += __shfl_xor_sync(0xffffffffu, p3, 8);

            float nm = fmaxf(m, fmaxf(fmaxf(p0, p1), fmaxf(p2, p3)));
            float f  = __expf(m - nm);
            float e0 = __expf(p0 - nm);
            float e1 = __expf(p1 - nm);
            float e2 = __expf(p2 - nm);
            float e3 = __expf(p3 - nm);
            den = den * f + (e0 + e1) + (e2 + e3);
            acc.x = acc.x * f + (e0 * x0.x + e1 * x1.x) + (e2 * x2.x + e3 * x3.x);
            acc.y = acc.y * f + (e0 * x0.y + e1 * x1.y) + (e2 * x2.y + e3 * x3.y);
            acc.z = acc.z * f + (e0 * x0.z + e1 * x1.z) + (e2 * x2.z + e3 * x3.z);
            acc.w = acc.w * f + (e0 * x0.w + e1 * x1.w) + (e2 * x2.w + e3 * x3.w);
            m = nm;
        }
        for (; t < cnt; t++) {              // tail edges of chunk
            int s0 = __shfl_sync(0xffffffffu, idx, t);
            float4 x0 = X4[s0 * 64 + lane];
            float p0 = lrelu(x0.x + xr4.x) * av.x + lrelu(x0.y + xr4.y) * av.y +
                       lrelu(x0.z + xr4.z) * av.z + lrelu(x0.w + xr4.w) * av.w;
            p0 += __shfl_xor_sync(0xffffffffu, p0, 1);
            p0 += __shfl_xor_sync(0xffffffffu, p0, 2);
            p0 += __shfl_xor_sync(0xffffffffu, p0, 4);
            p0 += __shfl_xor_sync(0xffffffffu, p0, 8);
            float nm = fmaxf(m, p0);
            float f  = __expf(m - nm);
            float e0 = __expf(p0 - nm);
            den = den * f + e0;
            acc.x = acc.x * f + e0 * x0.x;
            acc.y = acc.y * f + e0 * x0.y;
            acc.z = acc.z * f + e0 * x0.z;
            acc.w = acc.w * f + e0 * x0.w;
            m = nm;
        }
    }

    float inv = 1.f / den;
    float4 r = make_float4(acc.x * inv, acc.y * inv, acc.z * inv, acc.w * inv);
    float ox = __shfl_xor_sync(0xffffffffu, r.x, 16);
    float oy = __shfl_xor_sync(0xffffffffu, r.y, 16);
    float oz = __shfl_xor_sync(0xffffffffu, r.z, 16);
    float ow = __shfl_xor_sync(0xffffffffu, r.w, 16);
    if (lane < 16) {
        float4 b4 = ((const float4*)sbias)[lane];
        float4 g;
        g.x = 0.5f * (r.x + ox) + b4.x;
        g.y = 0.5f * (r.y + oy) + b4.y;
        g.z = 0.5f * (r.z + oz) + b4.z;
        g.w = 0.5f * (r.w + ow) + b4.w;
        ((float4*)d_g)[n * 16 + lane] = g;
        sg[w][lane * 4 + 0] = g.x;
        sg[w][lane * 4 + 1] = g.y;
        sg[w][lane * 4 + 2] = g.z;
        sg[w][lane * 4 + 3] = g.w;
    }
    __syncthreads();
    if (tid < 64) {                        // per-block BN partial stats
        float s = 0.f, ss = 0.f;
#pragma unroll
        for (int q = 0; q < 8; q++) { float v = sg[q][tid]; s += v; ss += v * v; }
        int slot = (blockIdx.x & (GS - 1)) * HID + tid;
        atomicAdd(&d_psum[slot], (double)s);
        atomicAdd(&d_psq[slot], (double)ss);
    }
}

// -------- output head: fused BN+ELU+residual, then 64->32 ELU ->1 sigmoid --
__global__ void k_head(const float* __restrict__ W1, const float* __restrict__ b1,
                       const float* __restrict__ W2, const float* __restrict__ b2,
                       float* __restrict__ out) {
    __shared__ float W1s[64 * 32];
    __shared__ float b1s[32];
    __shared__ float W2s[32];
    __shared__ float scs[64], shs[64];
    int tid = threadIdx.x;
    for (int f = tid; f < 2048; f += 128) W1s[f] = W1[f];
    if (tid < 32) { b1s[tid] = b1[tid]; W2s[tid] = W2[tid]; }
    if (tid < 64) { scs[tid] = d_scale[tid]; shs[tid] = d_shift[tid]; }
    __syncthreads();
    int n = blockIdx.x * 128 + tid;
    if (n >= NN) return;
    float acc[32];
#pragma unroll
    for (int jj = 0; jj < 32; jj++) acc[jj] = b1s[jj];
    const float4* G4 = (const float4*)d_g;
    const float4* H4 = (const float4*)d_h1;   // h_11 lives in d_h1 (layer 11 write)
#pragma unroll 4
    for (int k4 = 0; k4 < 16; k4++) {
        float4 gg = G4[n * 16 + k4];
        float4 ho = H4[n * 16 + k4];
        float hv[4];
        hv[0] = eluf(fmaf(gg.x, scs[k4 * 4 + 0], shs[k4 * 4 + 0])) + ho.x;
        hv[1] = eluf(fmaf(gg.y, scs[k4 * 4 + 1], shs[k4 * 4 + 1])) + ho.y;
        hv[2] = eluf(fmaf(gg.z, scs[k4 * 4 + 2], shs[k4 * 4 + 2])) + ho.z;
        hv[3] = eluf(fmaf(gg.w, scs[k4 * 4 + 3], shs[k4 * 4 + 3])) + ho.w;
#pragma unroll
        for (int q = 0; q < 4; q++) {
            float xv = hv[q];
            int k = k4 * 4 + q;
#pragma unroll
            for (int jj = 0; jj < 32; jj++) acc[jj] += xv * W1s[k * 32 + jj];
        }
    }
    float o = b2[0];
#pragma unroll
    for (int jj = 0; jj < 32; jj++) o += eluf(acc[jj]) * W2s[jj];
    out[n] = 1.f / (1.f + expf(-o));
}

// ---------------- launcher -------------------------------------------------
extern "C" void kernel_launch(void* const* d_in, const int* in_sizes, int n_in,
                              void* d_out, int out_size) {
    const float* x        = (const float*)d_in[0];
    const int*   ei       = (const int*)  d_in[1];
    const float* in_W     = (const float*)d_in[2];
    const float* in_b     = (const float*)d_in[3];
    const float* in_gamma = (const float*)d_in[4];
    const float* in_beta  = (const float*)d_in[5];
    const float* Wl       = (const float*)d_in[6];
    const float* Wr       = (const float*)d_in[7];
    const float* att      = (const float*)d_in[8];
    const float* cbias    = (const float*)d_in[9];
    const float* bn_gamma = (const float*)d_in[10];
    const float* bn_beta  = (const float*)d_in[11];
    const float* out_W1   = (const float*)d_in[12];
    const float* out_b1   = (const float*)d_in[13];
    const float* out_W2   = (const float*)d_in[14];
    const float* out_b2   = (const float*)d_in[15];
    float* out = (float*)d_out;

    dim3 tb64_4(64, 4);
    dim3 tb64_8(64, 8);
    dim3 gemm_grid((NN + 127) / 128, 4);

    // launch index 3 = layer-0 GEMM (ncu profiles launch #3)
    k_in_proj<<<GS, tb64_4>>>(x, in_W, in_b);                 // 0
    k_bn_prep<<<1, tb64_8>>>(in_gamma, in_beta);              // 1
    k_zero_deg<<<(NN + 255) / 256, 256>>>();                  // 2
    k_gemm<<<gemm_grid, 256>>>(Wl, Wr, 0);                    // 3 <- profiled

    // CSR build (once per launch, reused by all 12 layers)
    k_count<<<(ENT + 255) / 256, 256>>>(ei);
    k_scan1<<<SCAN_NB, SCAN_BLK>>>();
    k_scan2<<<1, 1>>>();
    k_scan3<<<SCAN_NB, SCAN_BLK>>>();
    k_scatter<<<(ENT + 255) / 256, 256>>>(ei);

    k_gat<<<NN / 8, 256>>>(att, cbias);
    k_bn_prep<<<1, tb64_8>>>(bn_gamma, bn_beta);

    for (int i = 1; i < 12; i++) {
        k_gemm<<<gemm_grid, 256>>>(Wl + i * HID * 128, Wr + i * HID * 128, i);
        k_gat<<<NN / 8, 256>>>(att + i * 128, cbias + i * HID);
        k_bn_prep<<<1, tb64_8>>>(bn_gamma + i * HID, bn_beta + i * HID);
    }

    k_head<<<(NN + 127) / 128, 128>>>(out_W1, out_b1, out_W2, out_b2, out);
}